// round 5
// baseline (speedup 1.0000x reference)
#include <cuda_runtime.h>

// Problem constants
#define B_    8
#define S_    1024
#define D_    768
#define H_    12
#define DK_   64
#define MROWS 8192                    // B*S
#define BSD   6291456                 // MROWS*D
#define BHSS  100663296LL             // B*H*S*S

#define NBLK  296                     // 2 x 148 SMs, guaranteed co-resident
#define NTHR  512

// Device-global scratch — used ONLY within a single kernel launch.
__device__ float g_q[BSD];
__device__ float g_k[BSD];
__device__ float g_v[BSD];
__device__ float g_ctx[BSD];
__device__ float g_proj[BSD];
__device__ float g_attn[(size_t)BHSS];

// Software grid barrier state (generation counter; replay-safe: gen only
// ever increments, count always returns to 0).
__device__ unsigned g_bar_count;
__device__ unsigned g_bar_gen;

__device__ __forceinline__ void grid_barrier() {
    __syncthreads();
    if (threadIdx.x == 0) {
        __threadfence();                      // make block's writes visible
        unsigned gen = g_bar_gen;             // snapshot before arriving
        unsigned old = atomicAdd(&g_bar_count, 1u);
        if (old == (unsigned)(gridDim.x - 1)) {
            g_bar_count = 0;                  // reset for next barrier
            __threadfence();
            atomicAdd(&g_bar_gen, 1u);        // release
        } else {
            while (atomicAdd(&g_bar_gen, 0u) == gen) { __nanosleep(64); }
        }
        __threadfence();                      // acquire
    }
    __syncthreads();
}

// ---------------------------------------------------------------------------
// Shared-memory tile helpers. All phases share the same static smem arrays.
//   sA, sB: 64x65-float tiles (16.6 KB each); sRed: 512-float reduction buf.
// Thread layout for tile compute: tx = tid&15 (4 cols each), ty = tid>>4
// (2 rows each) -> 64x64 tile, acc[2][4] per thread.
// ---------------------------------------------------------------------------

// One 64x64 output tile of out = A[8192,768] @ W[768,768] + bias.
// tileIdx in [0,1536): row0 = (t/12)*64, col0 = (t%12)*64.
__device__ void gemm_tile(const float* __restrict__ A, const float* __restrict__ W,
                          const float* __restrict__ bias, float* __restrict__ out,
                          int tileIdx, float* sA, float* sB) {
    const int row0 = (tileIdx / 12) * 64;
    const int col0 = (tileIdx % 12) * 64;
    const int tid = threadIdx.x;
    const int tx = tid & 15;
    const int ty = tid >> 4;

    float acc[2][4] = {};
    for (int k0 = 0; k0 < 768; k0 += 16) {
        #pragma unroll
        for (int e = 0; e < 2; e++) {
            int idx = tid + e * NTHR;          // 0..1023
            int m = idx >> 4, k = idx & 15;
            sA[k * 65 + m] = A[(size_t)(row0 + m) * 768 + (k0 + k)];
            int k2 = idx >> 6, n = idx & 63;
            sB[k2 * 65 + n] = W[(size_t)(k0 + k2) * 768 + (col0 + n)];
        }
        __syncthreads();
        #pragma unroll
        for (int k = 0; k < 16; k++) {
            float a0 = sA[k * 65 + ty * 2 + 0];
            float a1 = sA[k * 65 + ty * 2 + 1];
            #pragma unroll
            for (int j = 0; j < 4; j++) {
                float w = sB[k * 65 + tx * 4 + j];
                acc[0][j] = fmaf(a0, w, acc[0][j]);
                acc[1][j] = fmaf(a1, w, acc[1][j]);
            }
        }
        __syncthreads();
    }
    #pragma unroll
    for (int i = 0; i < 2; i++) {
        int r = row0 + ty * 2 + i;
        #pragma unroll
        for (int j = 0; j < 4; j++) {
            int c = col0 + tx * 4 + j;
            out[(size_t)r * 768 + c] = acc[i][j] + bias[c];
        }
    }
}

// One 64x64 score tile: g_attn[bh,i,j] = (1/8) sum_d q[b,i,h64+d]*k[b,j,h64+d]
// tileIdx in [0,24576): bh = t>>8; i0 = ((t&255)>>4)*64; j0 = (t&15)*64.
__device__ void score_tile(int tileIdx, float* sA, float* sB) {
    const int bh = tileIdx >> 8;
    const int r  = tileIdx & 255;
    const int i0 = (r >> 4) * 64;
    const int j0 = (r & 15) * 64;
    const int b  = bh / 12;
    const int h  = bh % 12;
    const float* qb = g_q + (size_t)b * S_ * 768 + h * 64;
    const float* kb = g_k + (size_t)b * S_ * 768 + h * 64;
    const int tid = threadIdx.x;
    const int tx = tid & 15;
    const int ty = tid >> 4;

    #pragma unroll
    for (int e = 0; e < 8; e++) {
        int idx = tid + e * NTHR;              // 0..4095
        int m = idx >> 6, d = idx & 63;
        sA[d * 65 + m] = qb[(size_t)(i0 + m) * 768 + d];
        sB[d * 65 + m] = kb[(size_t)(j0 + m) * 768 + d];
    }
    __syncthreads();

    float acc[2][4] = {};
    #pragma unroll
    for (int d = 0; d < 64; d++) {
        float a0 = sA[d * 65 + ty * 2 + 0];
        float a1 = sA[d * 65 + ty * 2 + 1];
        #pragma unroll
        for (int j = 0; j < 4; j++) {
            float k = sB[d * 65 + tx * 4 + j];
            acc[0][j] = fmaf(a0, k, acc[0][j]);
            acc[1][j] = fmaf(a1, k, acc[1][j]);
        }
    }
    __syncthreads();

    const size_t base = (size_t)bh * S_ * S_;
    #pragma unroll
    for (int i = 0; i < 2; i++)
        #pragma unroll
        for (int j = 0; j < 4; j++)
            g_attn[base + (size_t)(i0 + ty * 2 + i) * S_ + (j0 + tx * 4 + j)] =
                acc[i][j] * 0.125f;
}

// One 64x64 ctx tile: g_ctx[b, i, h64+n] = sum_j attn[bh,i,j] * v[b,j,h64+n]
// tileIdx in [0,1536): bh = t>>4; i0 = (t&15)*64.
__device__ void ctx_tile(int tileIdx, float* sA, float* sB) {
    const int bh = tileIdx >> 4;
    const int i0 = (tileIdx & 15) * 64;
    const int b  = bh / 12;
    const int h  = bh % 12;
    const float* ap = g_attn + (size_t)bh * S_ * S_;
    const float* vb = g_v + (size_t)b * S_ * 768 + h * 64;
    const int tid = threadIdx.x;
    const int tx = tid & 15;
    const int ty = tid >> 4;

    float acc[2][4] = {};
    for (int j0 = 0; j0 < S_; j0 += 16) {
        #pragma unroll
        for (int e = 0; e < 2; e++) {
            int idx = tid + e * NTHR;
            int m = idx >> 4, k = idx & 15;
            sA[k * 65 + m] = ap[(size_t)(i0 + m) * S_ + (j0 + k)];
            int k2 = idx >> 6, n = idx & 63;
            sB[k2 * 65 + n] = vb[(size_t)(j0 + k2) * 768 + n];
        }
        __syncthreads();
        #pragma unroll
        for (int k = 0; k < 16; k++) {
            float a0 = sA[k * 65 + ty * 2 + 0];
            float a1 = sA[k * 65 + ty * 2 + 1];
            #pragma unroll
            for (int j = 0; j < 4; j++) {
                float v = sB[k * 65 + tx * 4 + j];
                acc[0][j] = fmaf(a0, v, acc[0][j]);
                acc[1][j] = fmaf(a1, v, acc[1][j]);
            }
        }
        __syncthreads();
    }
    #pragma unroll
    for (int i = 0; i < 2; i++) {
        int s = i0 + ty * 2 + i;
        #pragma unroll
        for (int j = 0; j < 4; j++)
            g_ctx[(size_t)(b * S_ + s) * 768 + h * 64 + tx * 4 + j] = acc[i][j];
    }
}

// ---------------------------------------------------------------------------
// The single fused kernel: all phases, grid barriers between.
// ---------------------------------------------------------------------------
__global__ __launch_bounds__(NTHR, 2)
void fused_kernel(const float* __restrict__ query, const float* __restrict__ key,
                  const float* __restrict__ value, const float* __restrict__ mask,
                  const float* __restrict__ Wq, const float* __restrict__ bq,
                  const float* __restrict__ Wk, const float* __restrict__ bk,
                  const float* __restrict__ Wv, const float* __restrict__ bv,
                  const float* __restrict__ Wo, const float* __restrict__ bo,
                  const float* __restrict__ gamma, const float* __restrict__ beta,
                  float* __restrict__ out, float* __restrict__ attn_out) {
    __shared__ float sA[64 * 65];
    __shared__ float sB[64 * 65];
    __shared__ float sRed[NTHR];

    const int tid = threadIdx.x;

    // ---- Phase 1: QKV projections (3 x 1536 tile jobs) ----
    for (int job = blockIdx.x; job < 3 * 1536; job += gridDim.x) {
        int which = job / 1536;
        int t = job % 1536;
        const float* A = (which == 0) ? query : (which == 1) ? key : value;
        const float* W = (which == 0) ? Wq    : (which == 1) ? Wk  : Wv;
        const float* bb = (which == 0) ? bq   : (which == 1) ? bk  : bv;
        float* O = (which == 0) ? g_q : (which == 1) ? g_k : g_v;
        gemm_tile(A, W, bb, O, t, sA, sB);
    }
    grid_barrier();

    // ---- Phase 2: scores (24576 tile jobs) ----
    for (int t = blockIdx.x; t < 24576; t += gridDim.x)
        score_tile(t, sA, sB);
    grid_barrier();

    // ---- Phase 3: row softmax (98304 rows), in place + mirror to d_out ----
    for (long long row = blockIdx.x; row < 98304LL; row += gridDim.x) {
        const int b = (int)(row / 12288);        // H_*S_
        float* p = g_attn + (size_t)row * S_;
        const float* m = mask + (size_t)b * S_;

        float mx = -1e30f;
        #pragma unroll
        for (int e = 0; e < 2; e++) {
            int k = tid + e * NTHR;
            mx = fmaxf(mx, p[k] + (1.0f - m[k]) * -10000.0f);
        }
        sRed[tid] = mx;
        __syncthreads();
        for (int s = NTHR / 2; s > 0; s >>= 1) {
            if (tid < s) sRed[tid] = fmaxf(sRed[tid], sRed[tid + s]);
            __syncthreads();
        }
        mx = sRed[0];
        __syncthreads();

        float sum = 0.0f;
        #pragma unroll
        for (int e = 0; e < 2; e++) {
            int k = tid + e * NTHR;
            sum += __expf(p[k] + (1.0f - m[k]) * -10000.0f - mx);
        }
        sRed[tid] = sum;
        __syncthreads();
        for (int s = NTHR / 2; s > 0; s >>= 1) {
            if (tid < s) sRed[tid] += sRed[tid + s];
            __syncthreads();
        }
        const float inv = 1.0f / sRed[0];
        __syncthreads();

        #pragma unroll
        for (int e = 0; e < 2; e++) {
            int k = tid + e * NTHR;
            float prob = __expf(p[k] + (1.0f - m[k]) * -10000.0f - mx) * inv;
            p[k] = prob;
            if (attn_out) attn_out[(size_t)row * S_ + k] = prob;
        }
        __syncthreads();
    }
    grid_barrier();

    // ---- Phase 4: context (1536 tile jobs) ----
    for (int t = blockIdx.x; t < 1536; t += gridDim.x)
        ctx_tile(t, sA, sB);
    grid_barrier();

    // ---- Phase 5: output projection (1536 tile jobs) ----
    for (int t = blockIdx.x; t < 1536; t += gridDim.x)
        gemm_tile(g_ctx, Wo, bo, g_proj, t, sA, sB);
    grid_barrier();

    // ---- Phase 6: residual + LayerNorm (8192 rows) ----
    for (int row = blockIdx.x; row < MROWS; row += gridDim.x) {
        const float* pp = g_proj + (size_t)row * 768;
        const float* op = query + (size_t)row * 768;

        float lsum = 0.0f;
        for (int c = tid; c < 768; c += NTHR) {
            float x = pp[c] + op[c];
            sA[c] = x;                         // reuse sA as row cache
            lsum += x;
        }
        sRed[tid] = lsum;
        __syncthreads();
        for (int s = NTHR / 2; s > 0; s >>= 1) {
            if (tid < s) sRed[tid] += sRed[tid + s];
            __syncthreads();
        }
        const float mu = sRed[0] * (1.0f / 768.0f);
        __syncthreads();

        float lvar = 0.0f;
        for (int c = tid; c < 768; c += NTHR) {
            float d = sA[c] - mu;
            lvar += d * d;
        }
        sRed[tid] = lvar;
        __syncthreads();
        for (int s = NTHR / 2; s > 0; s >>= 1) {
            if (tid < s) sRed[tid] += sRed[tid + s];
            __syncthreads();
        }
        const float inv = rsqrtf(sRed[0] * (1.0f / 768.0f) + 1e-8f);
        __syncthreads();

        for (int c = tid; c < 768; c += NTHR)
            out[(size_t)row * 768 + c] = (sA[c] - mu) * inv * gamma[c] + beta[c];
        __syncthreads();
    }
}

// ---------------------------------------------------------------------------
// Launch
// ---------------------------------------------------------------------------
extern "C" void kernel_launch(void* const* d_in, const int* in_sizes, int n_in,
                              void* d_out, int out_size) {
    // Size-signature input binding (order-preserving within each size class).
    const float* big[3]  = {0, 0, 0};
    const float* mats[4] = {0, 0, 0, 0};
    const float* vecs[6] = {0, 0, 0, 0, 0, 0};
    const float* mask = 0;
    int nb = 0, nm = 0, nv = 0;
    for (int i = 0; i < n_in; i++) {
        const float* p = (const float*)d_in[i];
        switch (in_sizes[i]) {
            case 6291456: if (nb < 3) big[nb++] = p;  break;
            case 589824:  if (nm < 4) mats[nm++] = p; break;
            case 768:     if (nv < 6) vecs[nv++] = p; break;
            case 8192:    mask = p;                   break;
            default: break;
        }
    }
    float* out = (float*)d_out;
    float* attn_out = ((long long)out_size >= (long long)BSD + BHSS)
                          ? (out + BSD) : 0;

    fused_kernel<<<NBLK, NTHR>>>(big[0], big[1], big[2], mask,
                                 mats[0], vecs[0], mats[1], vecs[1],
                                 mats[2], vecs[2], mats[3], vecs[3],
                                 vecs[4], vecs[5], out, attn_out);
}

// round 6
// speedup vs baseline: 1.4615x; 1.4615x over previous
#include <cuda_runtime.h>

// Problem constants
#define B_    8
#define S_    1024
#define D_    768
#define H_    12
#define DK_   64
#define MROWS 8192                    // B*S
#define BSD   6291456                 // MROWS*D
#define BHSS  100663296LL             // B*H*S*S

#define NBLK  296                     // 2 x 148 SMs, co-resident
#define NTHR  512

// Device-global scratch — used ONLY within a single kernel launch.
__device__ float g_q[BSD];
__device__ float g_k[BSD];
__device__ float g_v[BSD];
__device__ float g_ctx[BSD];
__device__ float g_proj[BSD];
__device__ float g_attn[(size_t)BHSS];   // holds UNNORMALIZED exp after softmax
__device__ float g_inv[98304];           // per-row 1/sum

// Software grid barrier (generation counter; replay-safe).
__device__ unsigned g_bar_count;
__device__ unsigned g_bar_gen;

__device__ __forceinline__ void grid_barrier() {
    __syncthreads();
    if (threadIdx.x == 0) {
        __threadfence();
        unsigned gen = g_bar_gen;
        unsigned old = atomicAdd(&g_bar_count, 1u);
        if (old == (unsigned)(gridDim.x - 1)) {
            g_bar_count = 0;
            __threadfence();
            atomicAdd(&g_bar_gen, 1u);
        } else {
            while (atomicAdd(&g_bar_gen, 0u) == gen) { __nanosleep(64); }
        }
        __threadfence();
    }
    __syncthreads();
}

// tf32 conversion (round-to-nearest) — applied once during smem fill.
__device__ __forceinline__ float tf32r(float x) {
    unsigned u;
    asm("cvt.rna.tf32.f32 %0, %1;" : "=r"(u) : "f"(x));
    return __uint_as_float(u);
}

// One m16n8k8 tf32 mma, fp32 accumulate.
__device__ __forceinline__ void mma_tf32(float* acc, unsigned a0, unsigned a1,
                                         unsigned a2, unsigned a3,
                                         unsigned b0, unsigned b1) {
    asm volatile(
        "mma.sync.aligned.m16n8k8.row.col.f32.tf32.tf32.f32 "
        "{%0,%1,%2,%3}, {%4,%5,%6,%7}, {%8,%9}, {%0,%1,%2,%3};"
        : "+f"(acc[0]), "+f"(acc[1]), "+f"(acc[2]), "+f"(acc[3])
        : "r"(a0), "r"(a1), "r"(a2), "r"(a3), "r"(b0), "r"(b1));
}

// Per-warp 16x16 tile update over one 8-k slab starting at smem row ks.
// sA layout [k][m] (stride 65), sB layout [k][n] (stride 65).
__device__ __forceinline__ void warp_mma_step(const float* sA, const float* sB,
                                              int wm, int wn, int ks,
                                              int gid, int tig,
                                              float acc[2][4]) {
    unsigned a0 = __float_as_uint(sA[(ks + tig) * 65 + wm + gid]);
    unsigned a1 = __float_as_uint(sA[(ks + tig) * 65 + wm + gid + 8]);
    unsigned a2 = __float_as_uint(sA[(ks + tig + 4) * 65 + wm + gid]);
    unsigned a3 = __float_as_uint(sA[(ks + tig + 4) * 65 + wm + gid + 8]);
    #pragma unroll
    for (int nt = 0; nt < 2; nt++) {
        unsigned b0 = __float_as_uint(sB[(ks + tig) * 65 + wn + nt * 8 + gid]);
        unsigned b1 = __float_as_uint(sB[(ks + tig + 4) * 65 + wn + nt * 8 + gid]);
        mma_tf32(acc[nt], a0, a1, a2, a3, b0, b1);
    }
}

// ---------------------------------------------------------------------------
// One 64x64 tile of out = A[8192,768] @ W[768,768] + bias (tf32 mma).
// 512 threads = 16 warps, each warp a 16x16 subtile.
// ---------------------------------------------------------------------------
__device__ void gemm_tile(const float* __restrict__ A, const float* __restrict__ W,
                          const float* __restrict__ bias, float* __restrict__ out,
                          int tileIdx, float* sA, float* sB) {
    const int row0 = (tileIdx / 12) * 64;
    const int col0 = (tileIdx % 12) * 64;
    const int tid  = threadIdx.x;
    const int warp = tid >> 5, lane = tid & 31;
    const int gid  = lane >> 2, tig = lane & 3;
    const int wm   = (warp >> 2) * 16, wn = (warp & 3) * 16;

    float acc[2][4] = {};
    for (int k0 = 0; k0 < 768; k0 += 16) {
        #pragma unroll
        for (int e = 0; e < 2; e++) {
            int idx = tid + e * NTHR;           // 0..1023
            int m = idx >> 4, k = idx & 15;
            sA[k * 65 + m] = tf32r(A[(size_t)(row0 + m) * 768 + k0 + k]);
            int k2 = idx >> 6, n = idx & 63;
            sB[k2 * 65 + n] = tf32r(W[(size_t)(k0 + k2) * 768 + col0 + n]);
        }
        __syncthreads();
        warp_mma_step(sA, sB, wm, wn, 0, gid, tig, acc);
        warp_mma_step(sA, sB, wm, wn, 8, gid, tig, acc);
        __syncthreads();
    }

    const int r = row0 + wm + gid;
    #pragma unroll
    for (int nt = 0; nt < 2; nt++) {
        int c = col0 + wn + nt * 8 + tig * 2;
        out[(size_t)r * 768 + c]           = acc[nt][0] + bias[c];
        out[(size_t)r * 768 + c + 1]       = acc[nt][1] + bias[c + 1];
        out[(size_t)(r + 8) * 768 + c]     = acc[nt][2] + bias[c];
        out[(size_t)(r + 8) * 768 + c + 1] = acc[nt][3] + bias[c + 1];
    }
}

// ---------------------------------------------------------------------------
// One 64x64 score tile: g_attn[bh,i,j] = (1/8) q . k  (tf32 mma, K=64)
// ---------------------------------------------------------------------------
__device__ void score_tile(int tileIdx, float* sA, float* sB) {
    const int bh = tileIdx >> 8;
    const int r  = tileIdx & 255;
    const int i0 = (r >> 4) * 64;
    const int j0 = (r & 15) * 64;
    const int b  = bh / 12;
    const int h  = bh % 12;
    const float* qb = g_q + (size_t)b * S_ * 768 + h * 64;
    const float* kb = g_k + (size_t)b * S_ * 768 + h * 64;

    const int tid  = threadIdx.x;
    const int warp = tid >> 5, lane = tid & 31;
    const int gid  = lane >> 2, tig = lane & 3;
    const int wm   = (warp >> 2) * 16, wn = (warp & 3) * 16;

    #pragma unroll
    for (int e = 0; e < 8; e++) {
        int idx = tid + e * NTHR;               // 0..4095
        int m = idx >> 6, d = idx & 63;
        sA[d * 65 + m] = tf32r(qb[(size_t)(i0 + m) * 768 + d]);
        sB[d * 65 + m] = tf32r(kb[(size_t)(j0 + m) * 768 + d]);
    }
    __syncthreads();

    float acc[2][4] = {};
    #pragma unroll
    for (int ks = 0; ks < 64; ks += 8)
        warp_mma_step(sA, sB, wm, wn, ks, gid, tig, acc);
    __syncthreads();

    const size_t base = (size_t)bh * S_ * S_;
    const int ri = i0 + wm + gid;
    #pragma unroll
    for (int nt = 0; nt < 2; nt++) {
        int c = j0 + wn + nt * 8 + tig * 2;
        g_attn[base + (size_t)ri * S_ + c]           = acc[nt][0] * 0.125f;
        g_attn[base + (size_t)ri * S_ + c + 1]       = acc[nt][1] * 0.125f;
        g_attn[base + (size_t)(ri + 8) * S_ + c]     = acc[nt][2] * 0.125f;
        g_attn[base + (size_t)(ri + 8) * S_ + c + 1] = acc[nt][3] * 0.125f;
    }
}

// ---------------------------------------------------------------------------
// One 64x64 ctx tile: ctx[b,i,h64+n] = inv[i] * sum_j exp[bh,i,j] * v[b,j,h64+n]
// ---------------------------------------------------------------------------
__device__ void ctx_tile(int tileIdx, float* sA, float* sB) {
    const int bh = tileIdx >> 4;
    const int i0 = (tileIdx & 15) * 64;
    const int b  = bh / 12;
    const int h  = bh % 12;
    const float* ap = g_attn + (size_t)bh * S_ * S_;
    const float* vb = g_v + (size_t)b * S_ * 768 + h * 64;

    const int tid  = threadIdx.x;
    const int warp = tid >> 5, lane = tid & 31;
    const int gid  = lane >> 2, tig = lane & 3;
    const int wm   = (warp >> 2) * 16, wn = (warp & 3) * 16;

    float acc[2][4] = {};
    for (int jb = 0; jb < S_; jb += 16) {
        #pragma unroll
        for (int e = 0; e < 2; e++) {
            int idx = tid + e * NTHR;
            int m = idx >> 4, k = idx & 15;
            sA[k * 65 + m] = tf32r(ap[(size_t)(i0 + m) * S_ + jb + k]);
            int k2 = idx >> 6, n = idx & 63;
            sB[k2 * 65 + n] = tf32r(vb[(size_t)(jb + k2) * 768 + n]);
        }
        __syncthreads();
        warp_mma_step(sA, sB, wm, wn, 0, gid, tig, acc);
        warp_mma_step(sA, sB, wm, wn, 8, gid, tig, acc);
        __syncthreads();
    }

    const int s = i0 + wm + gid;
    const float inv0 = g_inv[bh * S_ + s];
    const float inv1 = g_inv[bh * S_ + s + 8];
    #pragma unroll
    for (int nt = 0; nt < 2; nt++) {
        int c = h * 64 + wn + nt * 8 + tig * 2;
        g_ctx[(size_t)(b * S_ + s) * 768 + c]           = acc[nt][0] * inv0;
        g_ctx[(size_t)(b * S_ + s) * 768 + c + 1]       = acc[nt][1] * inv0;
        g_ctx[(size_t)(b * S_ + s + 8) * 768 + c]       = acc[nt][2] * inv1;
        g_ctx[(size_t)(b * S_ + s + 8) * 768 + c + 1]   = acc[nt][3] * inv1;
    }
}

// ---------------------------------------------------------------------------
// The single fused kernel.
// ---------------------------------------------------------------------------
__global__ __launch_bounds__(NTHR, 2)
void fused_kernel(const float* __restrict__ query, const float* __restrict__ key,
                  const float* __restrict__ value, const float* __restrict__ mask,
                  const float* __restrict__ Wq, const float* __restrict__ bq,
                  const float* __restrict__ Wk, const float* __restrict__ bk,
                  const float* __restrict__ Wv, const float* __restrict__ bv,
                  const float* __restrict__ Wo, const float* __restrict__ bo,
                  const float* __restrict__ gamma, const float* __restrict__ beta,
                  float* __restrict__ out, float* __restrict__ attn_out) {
    __shared__ float sA[64 * 65];
    __shared__ float sB[64 * 65];
    __shared__ float sRed[NTHR];

    const int tid = threadIdx.x;

    // ---- Phase 1: QKV projections (3 x 1536 tile jobs) ----
    for (int job = blockIdx.x; job < 3 * 1536; job += gridDim.x) {
        int which = job / 1536;
        int t = job % 1536;
        const float* A  = (which == 0) ? query : (which == 1) ? key : value;
        const float* W  = (which == 0) ? Wq    : (which == 1) ? Wk  : Wv;
        const float* bb = (which == 0) ? bq    : (which == 1) ? bk  : bv;
        float* O        = (which == 0) ? g_q   : (which == 1) ? g_k : g_v;
        gemm_tile(A, W, bb, O, t, sA, sB);
    }
    grid_barrier();

    // ---- Phase 2: scores (24576 tile jobs) ----
    for (int t = blockIdx.x; t < 24576; t += gridDim.x)
        score_tile(t, sA, sB);
    grid_barrier();

    // ---- Phase 3: softmax — store unnormalized exp + 1/sum; mirror probs ----
    for (long long row = blockIdx.x; row < 98304LL; row += gridDim.x) {
        const int b = (int)(row / 12288);        // H_*S_
        float* p = g_attn + (size_t)row * S_;
        const float* m = mask + (size_t)b * S_;

        float mx = -1e30f;
        #pragma unroll
        for (int e = 0; e < 2; e++) {
            int k = tid + e * NTHR;
            mx = fmaxf(mx, p[k] + (1.0f - m[k]) * -10000.0f);
        }
        sRed[tid] = mx;
        __syncthreads();
        for (int s = NTHR / 2; s > 0; s >>= 1) {
            if (tid < s) sRed[tid] = fmaxf(sRed[tid], sRed[tid + s]);
            __syncthreads();
        }
        mx = sRed[0];
        __syncthreads();

        float sum = 0.0f;
        float ev[2];
        #pragma unroll
        for (int e = 0; e < 2; e++) {
            int k = tid + e * NTHR;
            ev[e] = __expf(p[k] + (1.0f - m[k]) * -10000.0f - mx);
            p[k] = ev[e];
            sum += ev[e];
        }
        sRed[tid] = sum;
        __syncthreads();
        for (int s = NTHR / 2; s > 0; s >>= 1) {
            if (tid < s) sRed[tid] += sRed[tid + s];
            __syncthreads();
        }
        const float inv = 1.0f / sRed[0];
        if (tid == 0) g_inv[row] = inv;
        __syncthreads();

        if (attn_out) {
            #pragma unroll
            for (int e = 0; e < 2; e++) {
                int k = tid + e * NTHR;
                attn_out[(size_t)row * S_ + k] = ev[e] * inv;
            }
        }
        __syncthreads();
    }
    grid_barrier();

    // ---- Phase 4: context (1536 tile jobs) ----
    for (int t = blockIdx.x; t < 1536; t += gridDim.x)
        ctx_tile(t, sA, sB);
    grid_barrier();

    // ---- Phase 5: output projection (1536 tile jobs) ----
    for (int t = blockIdx.x; t < 1536; t += gridDim.x)
        gemm_tile(g_ctx, Wo, bo, g_proj, t, sA, sB);
    grid_barrier();

    // ---- Phase 6: residual + LayerNorm (8192 rows) ----
    for (int row = blockIdx.x; row < MROWS; row += gridDim.x) {
        const float* pp = g_proj + (size_t)row * 768;
        const float* op = query + (size_t)row * 768;

        float lsum = 0.0f;
        for (int c = tid; c < 768; c += NTHR) {
            float x = pp[c] + op[c];
            sA[c] = x;
            lsum += x;
        }
        sRed[tid] = lsum;
        __syncthreads();
        for (int s = NTHR / 2; s > 0; s >>= 1) {
            if (tid < s) sRed[tid] += sRed[tid + s];
            __syncthreads();
        }
        const float mu = sRed[0] * (1.0f / 768.0f);
        __syncthreads();

        float lvar = 0.0f;
        for (int c = tid; c < 768; c += NTHR) {
            float d = sA[c] - mu;
            lvar += d * d;
        }
        sRed[tid] = lvar;
        __syncthreads();
        for (int s = NTHR / 2; s > 0; s >>= 1) {
            if (tid < s) sRed[tid] += sRed[tid + s];
            __syncthreads();
        }
        const float inv = rsqrtf(sRed[0] * (1.0f / 768.0f) + 1e-8f);
        __syncthreads();

        for (int c = tid; c < 768; c += NTHR)
            out[(size_t)row * 768 + c] = (sA[c] - mu) * inv * gamma[c] + beta[c];
        __syncthreads();
    }
}

// ---------------------------------------------------------------------------
// Launch
// ---------------------------------------------------------------------------
extern "C" void kernel_launch(void* const* d_in, const int* in_sizes, int n_in,
                              void* d_out, int out_size) {
    const float* big[3]  = {0, 0, 0};
    const float* mats[4] = {0, 0, 0, 0};
    const float* vecs[6] = {0, 0, 0, 0, 0, 0};
    const float* mask = 0;
    int nb = 0, nm = 0, nv = 0;
    for (int i = 0; i < n_in; i++) {
        const float* p = (const float*)d_in[i];
        switch (in_sizes[i]) {
            case 6291456: if (nb < 3) big[nb++] = p;  break;
            case 589824:  if (nm < 4) mats[nm++] = p; break;
            case 768:     if (nv < 6) vecs[nv++] = p; break;
            case 8192:    mask = p;                   break;
            default: break;
        }
    }
    float* out = (float*)d_out;
    float* attn_out = ((long long)out_size >= (long long)BSD + BHSS)
                          ? (out + BSD) : 0;

    fused_kernel<<<NBLK, NTHR>>>(big[0], big[1], big[2], mask,
                                 mats[0], vecs[0], mats[1], vecs[1],
                                 mats[2], vecs[2], mats[3], vecs[3],
                                 vecs[4], vecs[5], out, attn_out);
}

// round 7
// speedup vs baseline: 5.8173x; 3.9804x over previous
#include <cuda_runtime.h>

// Problem constants
#define B_    8
#define S_    1024
#define D_    768
#define H_    12
#define DK_   64
#define MROWS 8192                    // B*S
#define BSD   6291456                 // MROWS*D
#define BHSS  100663296LL             // B*H*S*S

#define NBLK  296                     // 2 per SM x 148 SMs, co-resident
#define NTHR  512
#define DYN_SMEM 69632                // score phase: 2 * 128 * 68 * 4

// Device-global scratch — used ONLY within a single kernel launch.
__device__ float g_q[BSD];
__device__ float g_k[BSD];
__device__ float g_v[BSD];
__device__ float g_ctx[BSD];
__device__ float g_proj[BSD];
__device__ float g_attn[(size_t)BHSS];   // unnormalized exp after softmax
__device__ float g_inv[98304];           // per-row 1/sum

// Software grid barrier (generation counter; replay-safe).
__device__ unsigned g_bar_count;
__device__ unsigned g_bar_gen;

__device__ __forceinline__ void grid_barrier() {
    __syncthreads();
    if (threadIdx.x == 0) {
        __threadfence();
        unsigned gen = g_bar_gen;
        unsigned old = atomicAdd(&g_bar_count, 1u);
        if (old == (unsigned)(gridDim.x - 1)) {
            g_bar_count = 0;
            __threadfence();
            atomicAdd(&g_bar_gen, 1u);
        } else {
            while (atomicAdd(&g_bar_gen, 0u) == gen) { __nanosleep(64); }
        }
        __threadfence();
    }
    __syncthreads();
}

__device__ __forceinline__ float tf32r(float x) {
    unsigned u;
    asm("cvt.rna.tf32.f32 %0, %1;" : "=r"(u) : "f"(x));
    return __uint_as_float(u);
}
__device__ __forceinline__ float4 tf32r4(float4 v) {
    v.x = tf32r(v.x); v.y = tf32r(v.y); v.z = tf32r(v.z); v.w = tf32r(v.w);
    return v;
}

__device__ __forceinline__ void mma_tf32(float* acc, unsigned a0, unsigned a1,
                                         unsigned a2, unsigned a3,
                                         unsigned b0, unsigned b1) {
    asm volatile(
        "mma.sync.aligned.m16n8k8.row.col.f32.tf32.tf32.f32 "
        "{%0,%1,%2,%3}, {%4,%5,%6,%7}, {%8,%9}, {%0,%1,%2,%3};"
        : "+f"(acc[0]), "+f"(acc[1]), "+f"(acc[2]), "+f"(acc[3])
        : "r"(a0), "r"(a1), "r"(a2), "r"(a3), "r"(b0), "r"(b1));
}
__device__ __forceinline__ unsigned fu(float x) { return __float_as_uint(x); }

// ---------------------------------------------------------------------------
// 128x128 GEMM tile, BK=32, tf32 mma. 16 warps (4x4), 32x32 per warp.
// sA: [m][k] stride 36; sB: [n][k] stride 36.
// out = A[8192,768] @ W[768,768] + bias. tileIdx: row0=(t/6)*128, col0=(t%6)*128.
// ---------------------------------------------------------------------------
__device__ void gemm_tile(const float* __restrict__ A, const float* __restrict__ W,
                          const float* __restrict__ bias, float* __restrict__ out,
                          int tileIdx, float* sA, float* sB) {
    const int row0 = (tileIdx / 6) * 128;
    const int col0 = (tileIdx % 6) * 128;
    const int tid  = threadIdx.x;
    const int warp = tid >> 5, lane = tid & 31;
    const int gid  = lane >> 2, tig = lane & 3;
    const int wm   = (warp >> 2) * 32, wn = (warp & 3) * 32;

    float acc[2][4][4] = {};

    for (int k0 = 0; k0 < 768; k0 += 32) {
        // fill A: [m][k], float4 per thread x2
        #pragma unroll
        for (int e = 0; e < 2; e++) {
            int idx = (e * NTHR + tid) * 4;      // 0..4095
            int m = idx >> 5, k = idx & 31;
            float4 v = *(const float4*)&A[(size_t)(row0 + m) * 768 + k0 + k];
            *(float4*)&sA[m * 36 + k] = tf32r4(v);
        }
        // fill B: [n][k] (transpose of W rows)
        {
            int n  = tid & 127;
            int kg = (tid >> 7) * 8;
            #pragma unroll
            for (int i = 0; i < 8; i++)
                sB[n * 36 + kg + i] =
                    tf32r(W[(size_t)(k0 + kg + i) * 768 + col0 + n]);
        }
        __syncthreads();

        #pragma unroll
        for (int ks = 0; ks < 32; ks += 8) {
            #pragma unroll
            for (int mt = 0; mt < 2; mt++) {
                const float* ap = &sA[(wm + mt * 16 + gid) * 36 + ks + tig];
                unsigned a0 = fu(ap[0]);
                unsigned a1 = fu(ap[8 * 36]);
                unsigned a2 = fu(ap[4]);
                unsigned a3 = fu(ap[8 * 36 + 4]);
                #pragma unroll
                for (int nt = 0; nt < 4; nt++) {
                    const float* bp = &sB[(wn + nt * 8 + gid) * 36 + ks + tig];
                    mma_tf32(acc[mt][nt], a0, a1, a2, a3, fu(bp[0]), fu(bp[4]));
                }
            }
        }
        __syncthreads();
    }

    #pragma unroll
    for (int mt = 0; mt < 2; mt++) {
        int r = row0 + wm + mt * 16 + gid;
        #pragma unroll
        for (int nt = 0; nt < 4; nt++) {
            int c = col0 + wn + nt * 8 + tig * 2;
            float2 v0 = {acc[mt][nt][0] + bias[c], acc[mt][nt][1] + bias[c + 1]};
            float2 v1 = {acc[mt][nt][2] + bias[c], acc[mt][nt][3] + bias[c + 1]};
            *(float2*)&out[(size_t)r * 768 + c]       = v0;
            *(float2*)&out[(size_t)(r + 8) * 768 + c] = v1;
        }
    }
}

// ---------------------------------------------------------------------------
// 128x128 score tile (K=64): g_attn[bh,i,j] = (1/8) q.k
// sQ: [m][d] stride 68; sK: [n][d] stride 68.
// tileIdx in [0,6144): bh=t/64; i0=((t%64)>>3)*128; j0=(t&7)*128.
// ---------------------------------------------------------------------------
__device__ void score_tile(int tileIdx, float* sQ, float* sK) {
    const int bh = tileIdx >> 6;
    const int r  = tileIdx & 63;
    const int i0 = (r >> 3) * 128;
    const int j0 = (r & 7) * 128;
    const int b  = bh / 12, h = bh % 12;
    const float* qb = g_q + (size_t)b * S_ * 768 + h * 64;
    const float* kb = g_k + (size_t)b * S_ * 768 + h * 64;

    const int tid  = threadIdx.x;
    const int warp = tid >> 5, lane = tid & 31;
    const int gid  = lane >> 2, tig = lane & 3;
    const int wm   = (warp >> 2) * 32, wn = (warp & 3) * 32;

    #pragma unroll
    for (int e = 0; e < 4; e++) {
        int idx = (e * NTHR + tid) * 4;          // 0..8191
        int m = idx >> 6, d = idx & 63;
        *(float4*)&sQ[m * 68 + d] =
            tf32r4(*(const float4*)&qb[(size_t)(i0 + m) * 768 + d]);
        *(float4*)&sK[m * 68 + d] =
            tf32r4(*(const float4*)&kb[(size_t)(j0 + m) * 768 + d]);
    }
    __syncthreads();

    float acc[2][4][4] = {};
    #pragma unroll
    for (int ks = 0; ks < 64; ks += 8) {
        #pragma unroll
        for (int mt = 0; mt < 2; mt++) {
            const float* ap = &sQ[(wm + mt * 16 + gid) * 68 + ks + tig];
            unsigned a0 = fu(ap[0]);
            unsigned a1 = fu(ap[8 * 68]);
            unsigned a2 = fu(ap[4]);
            unsigned a3 = fu(ap[8 * 68 + 4]);
            #pragma unroll
            for (int nt = 0; nt < 4; nt++) {
                const float* bp = &sK[(wn + nt * 8 + gid) * 68 + ks + tig];
                mma_tf32(acc[mt][nt], a0, a1, a2, a3, fu(bp[0]), fu(bp[4]));
            }
        }
    }
    __syncthreads();

    const size_t base = (size_t)bh * S_ * S_;
    #pragma unroll
    for (int mt = 0; mt < 2; mt++) {
        int ri = i0 + wm + mt * 16 + gid;
        #pragma unroll
        for (int nt = 0; nt < 4; nt++) {
            int c = j0 + wn + nt * 8 + tig * 2;
            float2 v0 = {acc[mt][nt][0] * 0.125f, acc[mt][nt][1] * 0.125f};
            float2 v1 = {acc[mt][nt][2] * 0.125f, acc[mt][nt][3] * 0.125f};
            *(float2*)&g_attn[base + (size_t)ri * S_ + c]       = v0;
            *(float2*)&g_attn[base + (size_t)(ri + 8) * S_ + c] = v1;
        }
    }
}

// ---------------------------------------------------------------------------
// 128x64 ctx tile (K=1024, BK=32): ctx = inv * (exp @ V)
// sP: [m][k] stride 36; sV: [n][k] stride 36. Warp tile 32x16.
// tileIdx in [0,768): bh=t>>3; i0=(t&7)*128.
// ---------------------------------------------------------------------------
__device__ void ctx_tile(int tileIdx, float* sP, float* sV) {
    const int bh = tileIdx >> 3;
    const int i0 = (tileIdx & 7) * 128;
    const int b  = bh / 12, h = bh % 12;
    const float* ap = g_attn + (size_t)bh * S_ * S_;
    const float* vb = g_v + (size_t)b * S_ * 768 + h * 64;

    const int tid  = threadIdx.x;
    const int warp = tid >> 5, lane = tid & 31;
    const int gid  = lane >> 2, tig = lane & 3;
    const int wm   = (warp >> 2) * 32, wn = (warp & 3) * 16;

    float acc[2][2][4] = {};

    for (int jb = 0; jb < S_; jb += 32) {
        #pragma unroll
        for (int e = 0; e < 2; e++) {
            int idx = (e * NTHR + tid) * 4;
            int m = idx >> 5, k = idx & 31;
            *(float4*)&sP[m * 36 + k] =
                tf32r4(*(const float4*)&ap[(size_t)(i0 + m) * S_ + jb + k]);
        }
        {
            int n  = tid & 63;
            int kg = (tid >> 6) * 4;
            #pragma unroll
            for (int i = 0; i < 4; i++)
                sV[n * 36 + kg + i] =
                    tf32r(vb[(size_t)(jb + kg + i) * 768 + n]);
        }
        __syncthreads();

        #pragma unroll
        for (int ks = 0; ks < 32; ks += 8) {
            #pragma unroll
            for (int mt = 0; mt < 2; mt++) {
                const float* app = &sP[(wm + mt * 16 + gid) * 36 + ks + tig];
                unsigned a0 = fu(app[0]);
                unsigned a1 = fu(app[8 * 36]);
                unsigned a2 = fu(app[4]);
                unsigned a3 = fu(app[8 * 36 + 4]);
                #pragma unroll
                for (int nt = 0; nt < 2; nt++) {
                    const float* bp = &sV[(wn + nt * 8 + gid) * 36 + ks + tig];
                    mma_tf32(acc[mt][nt], a0, a1, a2, a3, fu(bp[0]), fu(bp[4]));
                }
            }
        }
        __syncthreads();
    }

    #pragma unroll
    for (int mt = 0; mt < 2; mt++) {
        int s = i0 + wm + mt * 16 + gid;
        float inv0 = g_inv[bh * S_ + s];
        float inv1 = g_inv[bh * S_ + s + 8];
        #pragma unroll
        for (int nt = 0; nt < 2; nt++) {
            int c = h * 64 + wn + nt * 8 + tig * 2;
            float2 v0 = {acc[mt][nt][0] * inv0, acc[mt][nt][1] * inv0};
            float2 v1 = {acc[mt][nt][2] * inv1, acc[mt][nt][3] * inv1};
            *(float2*)&g_ctx[(size_t)(b * S_ + s) * 768 + c]       = v0;
            *(float2*)&g_ctx[(size_t)(b * S_ + s + 8) * 768 + c]   = v1;
        }
    }
}

// ---------------------------------------------------------------------------
// The single fused kernel.
// ---------------------------------------------------------------------------
__global__ __launch_bounds__(NTHR, 2)
void fused_kernel(const float* __restrict__ query, const float* __restrict__ key,
                  const float* __restrict__ value, const float* __restrict__ mask,
                  const float* __restrict__ Wq, const float* __restrict__ bq,
                  const float* __restrict__ Wk, const float* __restrict__ bk,
                  const float* __restrict__ Wv, const float* __restrict__ bv,
                  const float* __restrict__ Wo, const float* __restrict__ bo,
                  const float* __restrict__ gamma, const float* __restrict__ beta,
                  float* __restrict__ out, float* __restrict__ attn_out) {
    extern __shared__ float smem[];
    const int tid  = threadIdx.x;
    const int warp = tid >> 5, lane = tid & 31;

    // ---- Phase 1: QKV projections (3 x 384 tile jobs) ----
    for (int job = blockIdx.x; job < 3 * 384; job += NBLK) {
        int which = job / 384;
        int t = job % 384;
        const float* A  = (which == 0) ? query : (which == 1) ? key : value;
        const float* W  = (which == 0) ? Wq    : (which == 1) ? Wk  : Wv;
        const float* bb = (which == 0) ? bq    : (which == 1) ? bk  : bv;
        float* O        = (which == 0) ? g_q   : (which == 1) ? g_k : g_v;
        gemm_tile(A, W, bb, O, t, smem, smem + 128 * 36);
    }
    grid_barrier();

    // ---- Phase 2: scores (6144 tile jobs) ----
    for (int t = blockIdx.x; t < 6144; t += NBLK)
        score_tile(t, smem, smem + 128 * 68);
    grid_barrier();

    // ---- Phase 3: softmax — warp per row, shuffle reductions ----
    for (int row = blockIdx.x * 16 + warp; row < 98304; row += NBLK * 16) {
        const int b = row / 12288;                 // H*S
        float* p = g_attn + (size_t)row * S_;
        const float* m = mask + (size_t)b * S_;

        float4 val[8];
        float mx = -1e30f;
        #pragma unroll
        for (int v = 0; v < 8; v++) {
            int off = v * 128 + lane * 4;
            float4 s = *(float4*)&p[off];
            float4 mm = *(const float4*)&m[off];
            s.x += (1.0f - mm.x) * -10000.0f;
            s.y += (1.0f - mm.y) * -10000.0f;
            s.z += (1.0f - mm.z) * -10000.0f;
            s.w += (1.0f - mm.w) * -10000.0f;
            val[v] = s;
            mx = fmaxf(mx, fmaxf(fmaxf(s.x, s.y), fmaxf(s.z, s.w)));
        }
        #pragma unroll
        for (int o = 16; o > 0; o >>= 1)
            mx = fmaxf(mx, __shfl_xor_sync(0xFFFFFFFFu, mx, o));

        float sum = 0.0f;
        #pragma unroll
        for (int v = 0; v < 8; v++) {
            val[v].x = __expf(val[v].x - mx);
            val[v].y = __expf(val[v].y - mx);
            val[v].z = __expf(val[v].z - mx);
            val[v].w = __expf(val[v].w - mx);
            sum += val[v].x + val[v].y + val[v].z + val[v].w;
        }
        #pragma unroll
        for (int o = 16; o > 0; o >>= 1)
            sum += __shfl_xor_sync(0xFFFFFFFFu, sum, o);
        const float inv = 1.0f / sum;
        if (lane == 0) g_inv[row] = inv;

        #pragma unroll
        for (int v = 0; v < 8; v++) {
            int off = v * 128 + lane * 4;
            *(float4*)&p[off] = val[v];            // unnormalized exp
            if (attn_out) {
                float4 q = {val[v].x * inv, val[v].y * inv,
                            val[v].z * inv, val[v].w * inv};
                *(float4*)&attn_out[(size_t)row * S_ + off] = q;
            }
        }
    }
    grid_barrier();

    // ---- Phase 4: context (768 tile jobs) ----
    for (int t = blockIdx.x; t < 768; t += NBLK)
        ctx_tile(t, smem, smem + 128 * 36);
    grid_barrier();

    // ---- Phase 5: output projection (384 tile jobs) ----
    for (int t = blockIdx.x; t < 384; t += NBLK)
        gemm_tile(g_ctx, Wo, bo, g_proj, t, smem, smem + 128 * 36);
    grid_barrier();

    // ---- Phase 6: residual + LayerNorm — warp per row ----
    for (int row = blockIdx.x * 16 + warp; row < MROWS; row += NBLK * 16) {
        const float* pp = g_proj + (size_t)row * 768;
        const float* op = query + (size_t)row * 768;

        float4 x[6];
        float sum = 0.0f;
        #pragma unroll
        for (int v = 0; v < 6; v++) {
            int off = v * 128 + lane * 4;
            float4 a = *(const float4*)&pp[off];
            float4 o = *(const float4*)&op[off];
            x[v].x = a.x + o.x; x[v].y = a.y + o.y;
            x[v].z = a.z + o.z; x[v].w = a.w + o.w;
            sum += x[v].x + x[v].y + x[v].z + x[v].w;
        }
        #pragma unroll
        for (int o = 16; o > 0; o >>= 1)
            sum += __shfl_xor_sync(0xFFFFFFFFu, sum, o);
        const float mu = sum * (1.0f / 768.0f);

        float var = 0.0f;
        #pragma unroll
        for (int v = 0; v < 6; v++) {
            float dx = x[v].x - mu, dy = x[v].y - mu;
            float dz = x[v].z - mu, dw = x[v].w - mu;
            var += dx * dx + dy * dy + dz * dz + dw * dw;
        }
        #pragma unroll
        for (int o = 16; o > 0; o >>= 1)
            var += __shfl_xor_sync(0xFFFFFFFFu, var, o);
        const float inv = rsqrtf(var * (1.0f / 768.0f) + 1e-8f);

        #pragma unroll
        for (int v = 0; v < 6; v++) {
            int off = v * 128 + lane * 4;
            float4 g = *(const float4*)&gamma[off];
            float4 bt = *(const float4*)&beta[off];
            float4 r;
            r.x = (x[v].x - mu) * inv * g.x + bt.x;
            r.y = (x[v].y - mu) * inv * g.y + bt.y;
            r.z = (x[v].z - mu) * inv * g.z + bt.z;
            r.w = (x[v].w - mu) * inv * g.w + bt.w;
            *(float4*)&out[(size_t)row * 768 + off] = r;
        }
    }
}

// ---------------------------------------------------------------------------
// Launch
// ---------------------------------------------------------------------------
extern "C" void kernel_launch(void* const* d_in, const int* in_sizes, int n_in,
                              void* d_out, int out_size) {
    const float* big[3]  = {0, 0, 0};
    const float* mats[4] = {0, 0, 0, 0};
    const float* vecs[6] = {0, 0, 0, 0, 0, 0};
    const float* mask = 0;
    int nb = 0, nm = 0, nv = 0;
    for (int i = 0; i < n_in; i++) {
        const float* p = (const float*)d_in[i];
        switch (in_sizes[i]) {
            case 6291456: if (nb < 3) big[nb++] = p;  break;
            case 589824:  if (nm < 4) mats[nm++] = p; break;
            case 768:     if (nv < 6) vecs[nv++] = p; break;
            case 8192:    mask = p;                   break;
            default: break;
        }
    }
    float* out = (float*)d_out;
    float* attn_out = ((long long)out_size >= (long long)BSD + BHSS)
                          ? (out + BSD) : 0;

    cudaFuncSetAttribute(fused_kernel,
                         cudaFuncAttributeMaxDynamicSharedMemorySize, DYN_SMEM);

    fused_kernel<<<NBLK, NTHR, DYN_SMEM>>>(big[0], big[1], big[2], mask,
                                           mats[0], vecs[0], mats[1], vecs[1],
                                           mats[2], vecs[2], mats[3], vecs[3],
                                           vecs[4], vecs[5], out, attn_out);
}

// round 8
// speedup vs baseline: 6.1165x; 1.0514x over previous
#include <cuda_runtime.h>

// Problem constants
#define B_    8
#define S_    1024
#define D_    768
#define H_    12
#define DK_   64
#define MROWS 8192                    // B*S
#define BSD   6291456                 // MROWS*D
#define BHSS  100663296LL             // B*H*S*S

#define NBLK  296                     // 2 per SM x 148 SMs, co-resident
#define NTHR  512
#define DYN_SMEM 72192                // score phase: (2*128*68 + 512 + 128) * 4

// Device-global scratch — used ONLY within a single kernel launch.
__device__ float g_q[BSD];
__device__ float g_k[BSD];
__device__ float g_v[BSD];
__device__ float g_ctx[BSD];
__device__ float g_proj[BSD];
__device__ float g_attn[(size_t)BHSS];   // unnormalized exp(score)
__device__ float g_part[98304 * 8];      // per-row per-jtile partial sums
__device__ float g_inv[98304];           // per-row 1/sum

// Software grid barrier (generation counter; replay-safe).
__device__ unsigned g_bar_count;
__device__ unsigned g_bar_gen;

__device__ __forceinline__ void grid_barrier() {
    __syncthreads();
    if (threadIdx.x == 0) {
        __threadfence();
        unsigned gen = g_bar_gen;
        unsigned old = atomicAdd(&g_bar_count, 1u);
        if (old == (unsigned)(gridDim.x - 1)) {
            g_bar_count = 0;
            __threadfence();
            atomicAdd(&g_bar_gen, 1u);
        } else {
            while (atomicAdd(&g_bar_gen, 0u) == gen) { __nanosleep(64); }
        }
        __threadfence();
    }
    __syncthreads();
}

__device__ __forceinline__ float tf32r(float x) {
    unsigned u;
    asm("cvt.rna.tf32.f32 %0, %1;" : "=r"(u) : "f"(x));
    return __uint_as_float(u);
}
__device__ __forceinline__ float4 tf32r4(float4 v) {
    v.x = tf32r(v.x); v.y = tf32r(v.y); v.z = tf32r(v.z); v.w = tf32r(v.w);
    return v;
}

__device__ __forceinline__ void mma_tf32(float* acc, unsigned a0, unsigned a1,
                                         unsigned a2, unsigned a3,
                                         unsigned b0, unsigned b1) {
    asm volatile(
        "mma.sync.aligned.m16n8k8.row.col.f32.tf32.tf32.f32 "
        "{%0,%1,%2,%3}, {%4,%5,%6,%7}, {%8,%9}, {%0,%1,%2,%3};"
        : "+f"(acc[0]), "+f"(acc[1]), "+f"(acc[2]), "+f"(acc[3])
        : "r"(a0), "r"(a1), "r"(a2), "r"(a3), "r"(b0), "r"(b1));
}
__device__ __forceinline__ unsigned fu(float x) { return __float_as_uint(x); }

// ---------------------------------------------------------------------------
// 128x128 GEMM tile, BK=32, tf32 mma. 16 warps (4x4), 32x32 per warp.
// ---------------------------------------------------------------------------
__device__ void gemm_tile(const float* __restrict__ A, const float* __restrict__ W,
                          const float* __restrict__ bias, float* __restrict__ out,
                          int tileIdx, float* sA, float* sB) {
    const int row0 = (tileIdx / 6) * 128;
    const int col0 = (tileIdx % 6) * 128;
    const int tid  = threadIdx.x;
    const int warp = tid >> 5, lane = tid & 31;
    const int gid  = lane >> 2, tig = lane & 3;
    const int wm   = (warp >> 2) * 32, wn = (warp & 3) * 32;

    float acc[2][4][4] = {};

    for (int k0 = 0; k0 < 768; k0 += 32) {
        #pragma unroll
        for (int e = 0; e < 2; e++) {
            int idx = (e * NTHR + tid) * 4;
            int m = idx >> 5, k = idx & 31;
            float4 v = *(const float4*)&A[(size_t)(row0 + m) * 768 + k0 + k];
            *(float4*)&sA[m * 36 + k] = tf32r4(v);
        }
        {
            int n  = tid & 127;
            int kg = (tid >> 7) * 8;
            #pragma unroll
            for (int i = 0; i < 8; i++)
                sB[n * 36 + kg + i] =
                    tf32r(W[(size_t)(k0 + kg + i) * 768 + col0 + n]);
        }
        __syncthreads();

        #pragma unroll
        for (int ks = 0; ks < 32; ks += 8) {
            #pragma unroll
            for (int mt = 0; mt < 2; mt++) {
                const float* ap = &sA[(wm + mt * 16 + gid) * 36 + ks + tig];
                unsigned a0 = fu(ap[0]);
                unsigned a1 = fu(ap[8 * 36]);
                unsigned a2 = fu(ap[4]);
                unsigned a3 = fu(ap[8 * 36 + 4]);
                #pragma unroll
                for (int nt = 0; nt < 4; nt++) {
                    const float* bp = &sB[(wn + nt * 8 + gid) * 36 + ks + tig];
                    mma_tf32(acc[mt][nt], a0, a1, a2, a3, fu(bp[0]), fu(bp[4]));
                }
            }
        }
        __syncthreads();
    }

    #pragma unroll
    for (int mt = 0; mt < 2; mt++) {
        int r = row0 + wm + mt * 16 + gid;
        #pragma unroll
        for (int nt = 0; nt < 4; nt++) {
            int c = col0 + wn + nt * 8 + tig * 2;
            float2 v0 = {acc[mt][nt][0] + bias[c], acc[mt][nt][1] + bias[c + 1]};
            float2 v1 = {acc[mt][nt][2] + bias[c], acc[mt][nt][3] + bias[c + 1]};
            *(float2*)&out[(size_t)r * 768 + c]       = v0;
            *(float2*)&out[(size_t)(r + 8) * 768 + c] = v1;
        }
    }
}

// ---------------------------------------------------------------------------
// Fused score+exp tile (128x128, K=64):
//   E[bh,i,j] = exp(q.k/8 + (1-mask[j])*-1e4), written unnormalized to g_attn,
//   plus per-row partial sums -> g_part[row*8 + jtile].
// sQ: [m][d] str 68; sK: [n][d] str 68; sPart: [4][128]; sMask: [128].
// ---------------------------------------------------------------------------
__device__ void score_exp_tile(int tileIdx, const float* __restrict__ mask,
                               float* sQ, float* sK, float* sPart, float* sMask) {
    const int bh = tileIdx >> 6;
    const int r  = tileIdx & 63;
    const int i0 = (r >> 3) * 128;
    const int j0 = (r & 7) * 128;
    const int b  = bh / 12, h = bh % 12;
    const float* qb = g_q + (size_t)b * S_ * 768 + h * 64;
    const float* kb = g_k + (size_t)b * S_ * 768 + h * 64;

    const int tid  = threadIdx.x;
    const int warp = tid >> 5, lane = tid & 31;
    const int gid  = lane >> 2, tig = lane & 3;
    const int wm   = (warp >> 2) * 32, wn = (warp & 3) * 32;

    #pragma unroll
    for (int e = 0; e < 4; e++) {
        int idx = (e * NTHR + tid) * 4;
        int m = idx >> 6, d = idx & 63;
        *(float4*)&sQ[m * 68 + d] =
            tf32r4(*(const float4*)&qb[(size_t)(i0 + m) * 768 + d]);
        *(float4*)&sK[m * 68 + d] =
            tf32r4(*(const float4*)&kb[(size_t)(j0 + m) * 768 + d]);
    }
    if (tid < 128) sMask[tid] = mask[(size_t)b * S_ + j0 + tid];
    __syncthreads();

    float acc[2][4][4] = {};
    #pragma unroll
    for (int ks = 0; ks < 64; ks += 8) {
        #pragma unroll
        for (int mt = 0; mt < 2; mt++) {
            const float* ap = &sQ[(wm + mt * 16 + gid) * 68 + ks + tig];
            unsigned a0 = fu(ap[0]);
            unsigned a1 = fu(ap[8 * 68]);
            unsigned a2 = fu(ap[4]);
            unsigned a3 = fu(ap[8 * 68 + 4]);
            #pragma unroll
            for (int nt = 0; nt < 4; nt++) {
                const float* bp = &sK[(wn + nt * 8 + gid) * 68 + ks + tig];
                mma_tf32(acc[mt][nt], a0, a1, a2, a3, fu(bp[0]), fu(bp[4]));
            }
        }
    }
    __syncthreads();

    // exp on fragments, write E, reduce row sums
    const size_t base = (size_t)bh * S_ * S_;
    #pragma unroll
    for (int mt = 0; mt < 2; mt++) {
        int ri = i0 + wm + mt * 16 + gid;
        float rs0 = 0.0f, rs1 = 0.0f;
        #pragma unroll
        for (int nt = 0; nt < 4; nt++) {
            int lc = wn + nt * 8 + tig * 2;
            float mk0 = (1.0f - sMask[lc])     * -10000.0f;
            float mk1 = (1.0f - sMask[lc + 1]) * -10000.0f;
            float e0 = __expf(acc[mt][nt][0] * 0.125f + mk0);
            float e1 = __expf(acc[mt][nt][1] * 0.125f + mk1);
            float e2 = __expf(acc[mt][nt][2] * 0.125f + mk0);
            float e3 = __expf(acc[mt][nt][3] * 0.125f + mk1);
            rs0 += e0 + e1;
            rs1 += e2 + e3;
            float2 v0 = {e0, e1};
            float2 v1 = {e2, e3};
            *(float2*)&g_attn[base + (size_t)ri * S_ + j0 + lc]       = v0;
            *(float2*)&g_attn[base + (size_t)(ri + 8) * S_ + j0 + lc] = v1;
        }
        // reduce over the 4 tig lanes (same row, different j)
        #pragma unroll
        for (int o = 1; o < 4; o <<= 1) {
            rs0 += __shfl_xor_sync(0xFFFFFFFFu, rs0, o);
            rs1 += __shfl_xor_sync(0xFFFFFFFFu, rs1, o);
        }
        if (tig == 0) {
            sPart[(warp & 3) * 128 + wm + mt * 16 + gid]     = rs0;
            sPart[(warp & 3) * 128 + wm + mt * 16 + gid + 8] = rs1;
        }
    }
    __syncthreads();

    if (tid < 128) {
        float p = sPart[tid] + sPart[128 + tid] + sPart[256 + tid] + sPart[384 + tid];
        g_part[((size_t)bh * S_ + i0 + tid) * 8 + (j0 >> 7)] = p;
    }
    __syncthreads();
}

// ---------------------------------------------------------------------------
// 128x64 ctx tile (K=1024, BK=32): O = inv * (E @ V); also writes normalized
// probs (E*inv, fp32) to attn_out while reading E.
// sP: [m][k] str 36; sV: [n][k] str 36; sInv: [128].
// ---------------------------------------------------------------------------
__device__ void ctx_tile(int tileIdx, float* __restrict__ attn_out,
                         float* sP, float* sV, float* sInv) {
    const int bh = tileIdx >> 3;
    const int i0 = (tileIdx & 7) * 128;
    const int b  = bh / 12, h = bh % 12;
    const float* ap = g_attn + (size_t)bh * S_ * S_;
    const float* vb = g_v + (size_t)b * S_ * 768 + h * 64;

    const int tid  = threadIdx.x;
    const int warp = tid >> 5, lane = tid & 31;
    const int gid  = lane >> 2, tig = lane & 3;
    const int wm   = (warp >> 2) * 32, wn = (warp & 3) * 16;

    if (tid < 128) sInv[tid] = g_inv[(size_t)bh * S_ + i0 + tid];
    __syncthreads();

    float acc[2][2][4] = {};

    for (int jb = 0; jb < S_; jb += 32) {
        #pragma unroll
        for (int e = 0; e < 2; e++) {
            int idx = (e * NTHR + tid) * 4;
            int m = idx >> 5, k = idx & 31;
            size_t off = (size_t)(i0 + m) * S_ + jb + k;
            float4 ev = *(const float4*)&ap[off];
            if (attn_out) {
                float iv = sInv[m];
                float4 pr = {ev.x * iv, ev.y * iv, ev.z * iv, ev.w * iv};
                *(float4*)&attn_out[(size_t)bh * S_ * S_ + off] = pr;
            }
            *(float4*)&sP[m * 36 + k] = tf32r4(ev);
        }
        {
            int n  = tid & 63;
            int kg = (tid >> 6) * 4;
            #pragma unroll
            for (int i = 0; i < 4; i++)
                sV[n * 36 + kg + i] =
                    tf32r(vb[(size_t)(jb + kg + i) * 768 + n]);
        }
        __syncthreads();

        #pragma unroll
        for (int ks = 0; ks < 32; ks += 8) {
            #pragma unroll
            for (int mt = 0; mt < 2; mt++) {
                const float* app = &sP[(wm + mt * 16 + gid) * 36 + ks + tig];
                unsigned a0 = fu(app[0]);
                unsigned a1 = fu(app[8 * 36]);
                unsigned a2 = fu(app[4]);
                unsigned a3 = fu(app[8 * 36 + 4]);
                #pragma unroll
                for (int nt = 0; nt < 2; nt++) {
                    const float* bp = &sV[(wn + nt * 8 + gid) * 36 + ks + tig];
                    mma_tf32(acc[mt][nt], a0, a1, a2, a3, fu(bp[0]), fu(bp[4]));
                }
            }
        }
        __syncthreads();
    }

    #pragma unroll
    for (int mt = 0; mt < 2; mt++) {
        int sl = wm + mt * 16 + gid;
        int s = i0 + sl;
        float inv0 = sInv[sl];
        float inv1 = sInv[sl + 8];
        #pragma unroll
        for (int nt = 0; nt < 2; nt++) {
            int c = h * 64 + wn + nt * 8 + tig * 2;
            float2 v0 = {acc[mt][nt][0] * inv0, acc[mt][nt][1] * inv0};
            float2 v1 = {acc[mt][nt][2] * inv1, acc[mt][nt][3] * inv1};
            *(float2*)&g_ctx[(size_t)(b * S_ + s) * 768 + c]     = v0;
            *(float2*)&g_ctx[(size_t)(b * S_ + s + 8) * 768 + c] = v1;
        }
    }
    __syncthreads();
}

// ---------------------------------------------------------------------------
// The single fused kernel.
// ---------------------------------------------------------------------------
__global__ __launch_bounds__(NTHR, 2)
void fused_kernel(const float* __restrict__ query, const float* __restrict__ key,
                  const float* __restrict__ value, const float* __restrict__ mask,
                  const float* __restrict__ Wq, const float* __restrict__ bq,
                  const float* __restrict__ Wk, const float* __restrict__ bk,
                  const float* __restrict__ Wv, const float* __restrict__ bv,
                  const float* __restrict__ Wo, const float* __restrict__ bo,
                  const float* __restrict__ gamma, const float* __restrict__ beta,
                  float* __restrict__ out, float* __restrict__ attn_out) {
    extern __shared__ float smem[];
    const int tid  = threadIdx.x;
    const int warp = tid >> 5, lane = tid & 31;

    // smem layout (floats):
    //   score phase: sQ @0 (8704), sK @8704 (8704), sPart @17408 (512), sMask @17920 (128)
    //   gemm phase:  sA @0 (4608), sB @4608 (4608)
    //   ctx phase:   sP @0 (4608), sV @4608 (2304), sInv @6912 (128)

    // ---- Phase 1: QKV projections (3 x 384 tile jobs) ----
    for (int job = blockIdx.x; job < 3 * 384; job += NBLK) {
        int which = job / 384;
        int t = job % 384;
        const float* A  = (which == 0) ? query : (which == 1) ? key : value;
        const float* W  = (which == 0) ? Wq    : (which == 1) ? Wk  : Wv;
        const float* bb = (which == 0) ? bq    : (which == 1) ? bk  : bv;
        float* O        = (which == 0) ? g_q   : (which == 1) ? g_k : g_v;
        gemm_tile(A, W, bb, O, t, smem, smem + 128 * 36);
    }
    grid_barrier();

    // ---- Phase 2: fused score + exp + partial row sums (6144 jobs) ----
    for (int t = blockIdx.x; t < 6144; t += NBLK)
        score_exp_tile(t, mask, smem, smem + 8704, smem + 17408, smem + 17920);
    grid_barrier();

    // ---- Phase 3: per-row inverse sums (98304 rows; tiny) ----
    for (int row = blockIdx.x * NTHR + tid; row < 98304; row += NBLK * NTHR) {
        const float* pp = g_part + (size_t)row * 8;
        float4 a = *(const float4*)pp;
        float4 b4 = *(const float4*)(pp + 4);
        g_inv[row] = 1.0f / (a.x + a.y + a.z + a.w + b4.x + b4.y + b4.z + b4.w);
    }
    grid_barrier();

    // ---- Phase 4: context + normalized prob output (768 jobs) ----
    for (int t = blockIdx.x; t < 768; t += NBLK)
        ctx_tile(t, attn_out, smem, smem + 4608, smem + 6912);
    grid_barrier();

    // ---- Phase 5: output projection (384 jobs) ----
    for (int t = blockIdx.x; t < 384; t += NBLK)
        gemm_tile(g_ctx, Wo, bo, g_proj, t, smem, smem + 128 * 36);
    grid_barrier();

    // ---- Phase 6: residual + LayerNorm — warp per row ----
    for (int row = blockIdx.x * 16 + warp; row < MROWS; row += NBLK * 16) {
        const float* pp = g_proj + (size_t)row * 768;
        const float* op = query + (size_t)row * 768;

        float4 x[6];
        float sum = 0.0f;
        #pragma unroll
        for (int v = 0; v < 6; v++) {
            int off = v * 128 + lane * 4;
            float4 a = *(const float4*)&pp[off];
            float4 o = *(const float4*)&op[off];
            x[v].x = a.x + o.x; x[v].y = a.y + o.y;
            x[v].z = a.z + o.z; x[v].w = a.w + o.w;
            sum += x[v].x + x[v].y + x[v].z + x[v].w;
        }
        #pragma unroll
        for (int o = 16; o > 0; o >>= 1)
            sum += __shfl_xor_sync(0xFFFFFFFFu, sum, o);
        const float mu = sum * (1.0f / 768.0f);

        float var = 0.0f;
        #pragma unroll
        for (int v = 0; v < 6; v++) {
            float dx = x[v].x - mu, dy = x[v].y - mu;
            float dz = x[v].z - mu, dw = x[v].w - mu;
            var += dx * dx + dy * dy + dz * dz + dw * dw;
        }
        #pragma unroll
        for (int o = 16; o > 0; o >>= 1)
            var += __shfl_xor_sync(0xFFFFFFFFu, var, o);
        const float inv = rsqrtf(var * (1.0f / 768.0f) + 1e-8f);

        #pragma unroll
        for (int v = 0; v < 6; v++) {
            int off = v * 128 + lane * 4;
            float4 g = *(const float4*)&gamma[off];
            float4 bt = *(const float4*)&beta[off];
            float4 r;
            r.x = (x[v].x - mu) * inv * g.x + bt.x;
            r.y = (x[v].y - mu) * inv * g.y + bt.y;
            r.z = (x[v].z - mu) * inv * g.z + bt.z;
            r.w = (x[v].w - mu) * inv * g.w + bt.w;
            *(float4*)&out[(size_t)row * 768 + off] = r;
        }
    }
}

// ---------------------------------------------------------------------------
// Launch
// ---------------------------------------------------------------------------
extern "C" void kernel_launch(void* const* d_in, const int* in_sizes, int n_in,
                              void* d_out, int out_size) {
    const float* big[3]  = {0, 0, 0};
    const float* mats[4] = {0, 0, 0, 0};
    const float* vecs[6] = {0, 0, 0, 0, 0, 0};
    const float* mask = 0;
    int nb = 0, nm = 0, nv = 0;
    for (int i = 0; i < n_in; i++) {
        const float* p = (const float*)d_in[i];
        switch (in_sizes[i]) {
            case 6291456: if (nb < 3) big[nb++] = p;  break;
            case 589824:  if (nm < 4) mats[nm++] = p; break;
            case 768:     if (nv < 6) vecs[nv++] = p; break;
            case 8192:    mask = p;                   break;
            default: break;
        }
    }
    float* out = (float*)d_out;
    float* attn_out = ((long long)out_size >= (long long)BSD + BHSS)
                          ? (out + BSD) : 0;

    cudaFuncSetAttribute(fused_kernel,
                         cudaFuncAttributeMaxDynamicSharedMemorySize, DYN_SMEM);

    fused_kernel<<<NBLK, NTHR, DYN_SMEM>>>(big[0], big[1], big[2], mask,
                                           mats[0], vecs[0], mats[1], vecs[1],
                                           mats[2], vecs[2], mats[3], vecs[3],
                                           vecs[4], vecs[5], out, attn_out);
}

// round 9
// speedup vs baseline: 7.1009x; 1.1609x over previous
#include <cuda_runtime.h>
#include <cuda_bf16.h>

// Problem constants
#define B_    8
#define S_    1024
#define D_    768
#define H_    12
#define DK_   64
#define MROWS 8192                    // B*S
#define BSD   6291456                 // MROWS*D
#define BHSS  100663296LL             // B*H*S*S

#define NBLK  296                     // 2 per SM x 148 SMs, co-resident
#define NTHR  512
#define DYN_SMEM 72192                // score phase: (2*128*68 + 512 + 128) * 4

// Device-global scratch — used ONLY within a single kernel launch.
__device__ float g_q[BSD];
__device__ float g_k[BSD];
__device__ float g_v[BSD];
__device__ float g_ctx[BSD];
__device__ float g_proj[BSD];
__device__ float g_attn[(size_t)BHSS];   // unnormalized exp(score)
__device__ float g_part[98304 * 8];      // per-row per-jtile partial sums
__device__ float g_inv[98304];           // per-row 1/sum

// Software grid barrier (generation counter; replay-safe).
__device__ unsigned g_bar_count;
__device__ unsigned g_bar_gen;

__device__ __forceinline__ void grid_barrier() {
    __syncthreads();
    if (threadIdx.x == 0) {
        __threadfence();
        unsigned gen = g_bar_gen;
        unsigned old = atomicAdd(&g_bar_count, 1u);
        if (old == (unsigned)(gridDim.x - 1)) {
            g_bar_count = 0;
            __threadfence();
            atomicAdd(&g_bar_gen, 1u);
        } else {
            while (atomicAdd(&g_bar_gen, 0u) == gen) { __nanosleep(64); }
        }
        __threadfence();
    }
    __syncthreads();
}

__device__ __forceinline__ float tf32r(float x) {
    unsigned u;
    asm("cvt.rna.tf32.f32 %0, %1;" : "=r"(u) : "f"(x));
    return __uint_as_float(u);
}
__device__ __forceinline__ float4 tf32r4(float4 v) {
    v.x = tf32r(v.x); v.y = tf32r(v.y); v.z = tf32r(v.z); v.w = tf32r(v.w);
    return v;
}
__device__ __forceinline__ unsigned bf2(float a, float b) {
    __nv_bfloat162 h = __floats2bfloat162_rn(a, b);
    return *(unsigned*)&h;
}

__device__ __forceinline__ void mma_tf32(float* acc, unsigned a0, unsigned a1,
                                         unsigned a2, unsigned a3,
                                         unsigned b0, unsigned b1) {
    asm volatile(
        "mma.sync.aligned.m16n8k8.row.col.f32.tf32.tf32.f32 "
        "{%0,%1,%2,%3}, {%4,%5,%6,%7}, {%8,%9}, {%0,%1,%2,%3};"
        : "+f"(acc[0]), "+f"(acc[1]), "+f"(acc[2]), "+f"(acc[3])
        : "r"(a0), "r"(a1), "r"(a2), "r"(a3), "r"(b0), "r"(b1));
}
__device__ __forceinline__ void mma_bf16(float* acc, unsigned a0, unsigned a1,
                                         unsigned a2, unsigned a3,
                                         unsigned b0, unsigned b1) {
    asm volatile(
        "mma.sync.aligned.m16n8k16.row.col.f32.bf16.bf16.f32 "
        "{%0,%1,%2,%3}, {%4,%5,%6,%7}, {%8,%9}, {%0,%1,%2,%3};"
        : "+f"(acc[0]), "+f"(acc[1]), "+f"(acc[2]), "+f"(acc[3])
        : "r"(a0), "r"(a1), "r"(a2), "r"(a3), "r"(b0), "r"(b1));
}
__device__ __forceinline__ unsigned fu(float x) { return __float_as_uint(x); }

// ---------------------------------------------------------------------------
// 128x128 tf32 GEMM tile, BK=64. sA:[m][k] str 68; sB:[n][k] str 68.
// 16 warps (4x4), 32x32 per warp. Used for QKV projections.
// ---------------------------------------------------------------------------
__device__ void gemm_tile_tf32(const float* __restrict__ A,
                               const float* __restrict__ W,
                               const float* __restrict__ bias,
                               float* __restrict__ out,
                               int tileIdx, float* sA, float* sB) {
    const int row0 = (tileIdx / 6) * 128;
    const int col0 = (tileIdx % 6) * 128;
    const int tid  = threadIdx.x;
    const int warp = tid >> 5, lane = tid & 31;
    const int gid  = lane >> 2, tig = lane & 3;
    const int wm   = (warp >> 2) * 32, wn = (warp & 3) * 32;

    float acc[2][4][4] = {};

    for (int k0 = 0; k0 < 768; k0 += 64) {
        #pragma unroll
        for (int e = 0; e < 4; e++) {
            int idx = (e * NTHR + tid) * 4;      // 0..8191
            int m = idx >> 6, k = idx & 63;
            float4 v = *(const float4*)&A[(size_t)(row0 + m) * 768 + k0 + k];
            *(float4*)&sA[m * 68 + k] = tf32r4(v);
        }
        {
            int n  = tid & 127;
            int kg = (tid >> 7) * 16;
            #pragma unroll
            for (int g = 0; g < 4; g++) {
                float4 w;
                w.x = W[(size_t)(k0 + kg + g * 4 + 0) * 768 + col0 + n];
                w.y = W[(size_t)(k0 + kg + g * 4 + 1) * 768 + col0 + n];
                w.z = W[(size_t)(k0 + kg + g * 4 + 2) * 768 + col0 + n];
                w.w = W[(size_t)(k0 + kg + g * 4 + 3) * 768 + col0 + n];
                // store transposed: sB[n][kg+g*4 .. +3]
                sB[n * 68 + kg + g * 4 + 0] = tf32r(w.x);
                sB[n * 68 + kg + g * 4 + 1] = tf32r(w.y);
                sB[n * 68 + kg + g * 4 + 2] = tf32r(w.z);
                sB[n * 68 + kg + g * 4 + 3] = tf32r(w.w);
            }
        }
        __syncthreads();

        #pragma unroll
        for (int ks = 0; ks < 64; ks += 8) {
            unsigned b0[4], b1[4];
            #pragma unroll
            for (int nt = 0; nt < 4; nt++) {
                const float* bp = &sB[(wn + nt * 8 + gid) * 68 + ks + tig];
                b0[nt] = fu(bp[0]);
                b1[nt] = fu(bp[4]);
            }
            #pragma unroll
            for (int mt = 0; mt < 2; mt++) {
                const float* ap = &sA[(wm + mt * 16 + gid) * 68 + ks + tig];
                unsigned a0 = fu(ap[0]);
                unsigned a1 = fu(ap[8 * 68]);
                unsigned a2 = fu(ap[4]);
                unsigned a3 = fu(ap[8 * 68 + 4]);
                #pragma unroll
                for (int nt = 0; nt < 4; nt++)
                    mma_tf32(acc[mt][nt], a0, a1, a2, a3, b0[nt], b1[nt]);
            }
        }
        __syncthreads();
    }

    #pragma unroll
    for (int mt = 0; mt < 2; mt++) {
        int r = row0 + wm + mt * 16 + gid;
        #pragma unroll
        for (int nt = 0; nt < 4; nt++) {
            int c = col0 + wn + nt * 8 + tig * 2;
            float2 v0 = {acc[mt][nt][0] + bias[c], acc[mt][nt][1] + bias[c + 1]};
            float2 v1 = {acc[mt][nt][2] + bias[c], acc[mt][nt][3] + bias[c + 1]};
            *(float2*)&out[(size_t)r * 768 + c]       = v0;
            *(float2*)&out[(size_t)(r + 8) * 768 + c] = v1;
        }
    }
}

// ---------------------------------------------------------------------------
// 128x128 bf16 GEMM tile (m16n8k16), BK=64. Used for the O projection only
// (errors damped by the residual). sA16/sB16: bf16, [.][k] str 72.
// ---------------------------------------------------------------------------
__device__ void gemm_tile_bf16(const float* __restrict__ A,
                               const float* __restrict__ W,
                               const float* __restrict__ bias,
                               float* __restrict__ out,
                               int tileIdx, float* smem) {
    __nv_bfloat16* sA16 = (__nv_bfloat16*)smem;            // 128*72
    __nv_bfloat16* sB16 = (__nv_bfloat16*)(smem + 4608);   // 128*72

    const int row0 = (tileIdx / 6) * 128;
    const int col0 = (tileIdx % 6) * 128;
    const int tid  = threadIdx.x;
    const int warp = tid >> 5, lane = tid & 31;
    const int gid  = lane >> 2, tig = lane & 3;
    const int wm   = (warp >> 2) * 32, wn = (warp & 3) * 32;

    float acc[2][4][4] = {};

    for (int k0 = 0; k0 < 768; k0 += 64) {
        #pragma unroll
        for (int e = 0; e < 4; e++) {
            int idx = (e * NTHR + tid) * 4;
            int m = idx >> 6, k = idx & 63;
            float4 v = *(const float4*)&A[(size_t)(row0 + m) * 768 + k0 + k];
            uint2 u = {bf2(v.x, v.y), bf2(v.z, v.w)};
            *(uint2*)&sA16[m * 72 + k] = u;
        }
        {
            int n  = tid & 127;
            int kg = (tid >> 7) * 16;
            #pragma unroll
            for (int g = 0; g < 2; g++) {
                float w[8];
                #pragma unroll
                for (int i = 0; i < 8; i++)
                    w[i] = W[(size_t)(k0 + kg + g * 8 + i) * 768 + col0 + n];
                uint4 u = {bf2(w[0], w[1]), bf2(w[2], w[3]),
                           bf2(w[4], w[5]), bf2(w[6], w[7])};
                *(uint4*)&sB16[n * 72 + kg + g * 8] = u;
            }
        }
        __syncthreads();

        #pragma unroll
        for (int ks = 0; ks < 64; ks += 16) {
            unsigned b0[4], b1[4];
            #pragma unroll
            for (int nt = 0; nt < 4; nt++) {
                const __nv_bfloat16* bp = &sB16[(wn + nt * 8 + gid) * 72 + ks + tig * 2];
                b0[nt] = *(const unsigned*)bp;
                b1[nt] = *(const unsigned*)(bp + 8);
            }
            #pragma unroll
            for (int mt = 0; mt < 2; mt++) {
                const __nv_bfloat16* ap = &sA16[(wm + mt * 16 + gid) * 72 + ks + tig * 2];
                unsigned a0 = *(const unsigned*)ap;
                unsigned a1 = *(const unsigned*)(ap + 8 * 72);
                unsigned a2 = *(const unsigned*)(ap + 8);
                unsigned a3 = *(const unsigned*)(ap + 8 * 72 + 8);
                #pragma unroll
                for (int nt = 0; nt < 4; nt++)
                    mma_bf16(acc[mt][nt], a0, a1, a2, a3, b0[nt], b1[nt]);
            }
        }
        __syncthreads();
    }

    #pragma unroll
    for (int mt = 0; mt < 2; mt++) {
        int r = row0 + wm + mt * 16 + gid;
        #pragma unroll
        for (int nt = 0; nt < 4; nt++) {
            int c = col0 + wn + nt * 8 + tig * 2;
            float2 v0 = {acc[mt][nt][0] + bias[c], acc[mt][nt][1] + bias[c + 1]};
            float2 v1 = {acc[mt][nt][2] + bias[c], acc[mt][nt][3] + bias[c + 1]};
            *(float2*)&out[(size_t)r * 768 + c]       = v0;
            *(float2*)&out[(size_t)(r + 8) * 768 + c] = v1;
        }
    }
}

// ---------------------------------------------------------------------------
// Fused score+exp tile (128x128, K=64, tf32) — identical math to round 8.
// ---------------------------------------------------------------------------
__device__ void score_exp_tile(int tileIdx, const float* __restrict__ mask,
                               float* sQ, float* sK, float* sPart, float* sMask) {
    const int bh = tileIdx >> 6;
    const int r  = tileIdx & 63;
    const int i0 = (r >> 3) * 128;
    const int j0 = (r & 7) * 128;
    const int b  = bh / 12, h = bh % 12;
    const float* qb = g_q + (size_t)b * S_ * 768 + h * 64;
    const float* kb = g_k + (size_t)b * S_ * 768 + h * 64;

    const int tid  = threadIdx.x;
    const int warp = tid >> 5, lane = tid & 31;
    const int gid  = lane >> 2, tig = lane & 3;
    const int wm   = (warp >> 2) * 32, wn = (warp & 3) * 32;

    #pragma unroll
    for (int e = 0; e < 4; e++) {
        int idx = (e * NTHR + tid) * 4;
        int m = idx >> 6, d = idx & 63;
        *(float4*)&sQ[m * 68 + d] =
            tf32r4(*(const float4*)&qb[(size_t)(i0 + m) * 768 + d]);
        *(float4*)&sK[m * 68 + d] =
            tf32r4(*(const float4*)&kb[(size_t)(j0 + m) * 768 + d]);
    }
    if (tid < 128) sMask[tid] = mask[(size_t)b * S_ + j0 + tid];
    __syncthreads();

    float acc[2][4][4] = {};
    #pragma unroll
    for (int ks = 0; ks < 64; ks += 8) {
        unsigned b0[4], b1[4];
        #pragma unroll
        for (int nt = 0; nt < 4; nt++) {
            const float* bp = &sK[(wn + nt * 8 + gid) * 68 + ks + tig];
            b0[nt] = fu(bp[0]);
            b1[nt] = fu(bp[4]);
        }
        #pragma unroll
        for (int mt = 0; mt < 2; mt++) {
            const float* ap = &sQ[(wm + mt * 16 + gid) * 68 + ks + tig];
            unsigned a0 = fu(ap[0]);
            unsigned a1 = fu(ap[8 * 68]);
            unsigned a2 = fu(ap[4]);
            unsigned a3 = fu(ap[8 * 68 + 4]);
            #pragma unroll
            for (int nt = 0; nt < 4; nt++)
                mma_tf32(acc[mt][nt], a0, a1, a2, a3, b0[nt], b1[nt]);
        }
    }
    __syncthreads();

    const size_t base = (size_t)bh * S_ * S_;
    #pragma unroll
    for (int mt = 0; mt < 2; mt++) {
        int ri = i0 + wm + mt * 16 + gid;
        float rs0 = 0.0f, rs1 = 0.0f;
        #pragma unroll
        for (int nt = 0; nt < 4; nt++) {
            int lc = wn + nt * 8 + tig * 2;
            float mk0 = (1.0f - sMask[lc])     * -10000.0f;
            float mk1 = (1.0f - sMask[lc + 1]) * -10000.0f;
            float e0 = __expf(acc[mt][nt][0] * 0.125f + mk0);
            float e1 = __expf(acc[mt][nt][1] * 0.125f + mk1);
            float e2 = __expf(acc[mt][nt][2] * 0.125f + mk0);
            float e3 = __expf(acc[mt][nt][3] * 0.125f + mk1);
            rs0 += e0 + e1;
            rs1 += e2 + e3;
            float2 v0 = {e0, e1};
            float2 v1 = {e2, e3};
            *(float2*)&g_attn[base + (size_t)ri * S_ + j0 + lc]       = v0;
            *(float2*)&g_attn[base + (size_t)(ri + 8) * S_ + j0 + lc] = v1;
        }
        #pragma unroll
        for (int o = 1; o < 4; o <<= 1) {
            rs0 += __shfl_xor_sync(0xFFFFFFFFu, rs0, o);
            rs1 += __shfl_xor_sync(0xFFFFFFFFu, rs1, o);
        }
        if (tig == 0) {
            sPart[(warp & 3) * 128 + wm + mt * 16 + gid]     = rs0;
            sPart[(warp & 3) * 128 + wm + mt * 16 + gid + 8] = rs1;
        }
    }
    __syncthreads();

    if (tid < 128) {
        float p = sPart[tid] + sPart[128 + tid] + sPart[256 + tid] + sPart[384 + tid];
        g_part[((size_t)bh * S_ + i0 + tid) * 8 + (j0 >> 7)] = p;
    }
    __syncthreads();
}

// ---------------------------------------------------------------------------
// 128x64 ctx tile, BK=64, bf16 mma (m16n8k16): O = inv * (E @ V).
// Probs output written fp32 from the fp32 E read (accuracy path unchanged).
// sP: bf16 [128][72]; sV: bf16 [64][72]; sInv: float[128].
// ---------------------------------------------------------------------------
__device__ void ctx_tile(int tileIdx, float* __restrict__ attn_out,
                         float* smem) {
    __nv_bfloat16* sP = (__nv_bfloat16*)smem;              // 128*72 bf16
    __nv_bfloat16* sV = (__nv_bfloat16*)(smem + 4608);     // 64*72 bf16
    float* sInv = smem + 6912;                             // 128 floats

    const int bh = tileIdx >> 3;
    const int i0 = (tileIdx & 7) * 128;
    const int b  = bh / 12, h = bh % 12;
    const float* ap = g_attn + (size_t)bh * S_ * S_;
    const float* vb = g_v + (size_t)b * S_ * 768 + h * 64;

    const int tid  = threadIdx.x;
    const int warp = tid >> 5, lane = tid & 31;
    const int gid  = lane >> 2, tig = lane & 3;
    const int wm   = (warp >> 2) * 32, wn = (warp & 3) * 16;

    if (tid < 128) sInv[tid] = g_inv[(size_t)bh * S_ + i0 + tid];
    __syncthreads();

    float acc[2][2][4] = {};

    for (int jb = 0; jb < S_; jb += 64) {
        #pragma unroll
        for (int e = 0; e < 4; e++) {
            int idx = (e * NTHR + tid) * 4;
            int m = idx >> 6, k = idx & 63;
            size_t off = (size_t)(i0 + m) * S_ + jb + k;
            float4 ev = *(const float4*)&ap[off];
            if (attn_out) {
                float iv = sInv[m];
                float4 pr = {ev.x * iv, ev.y * iv, ev.z * iv, ev.w * iv};
                *(float4*)&attn_out[(size_t)bh * S_ * S_ + off] = pr;
            }
            uint2 u = {bf2(ev.x, ev.y), bf2(ev.z, ev.w)};
            *(uint2*)&sP[m * 72 + k] = u;
        }
        {
            int n  = tid & 63;
            int kg = (tid >> 6) * 8;
            float w[8];
            #pragma unroll
            for (int i = 0; i < 8; i++)
                w[i] = vb[(size_t)(jb + kg + i) * 768 + n];
            uint4 u = {bf2(w[0], w[1]), bf2(w[2], w[3]),
                       bf2(w[4], w[5]), bf2(w[6], w[7])};
            *(uint4*)&sV[n * 72 + kg] = u;
        }
        __syncthreads();

        #pragma unroll
        for (int ks = 0; ks < 64; ks += 16) {
            unsigned b0[2], b1[2];
            #pragma unroll
            for (int nt = 0; nt < 2; nt++) {
                const __nv_bfloat16* bp = &sV[(wn + nt * 8 + gid) * 72 + ks + tig * 2];
                b0[nt] = *(const unsigned*)bp;
                b1[nt] = *(const unsigned*)(bp + 8);
            }
            #pragma unroll
            for (int mt = 0; mt < 2; mt++) {
                const __nv_bfloat16* app = &sP[(wm + mt * 16 + gid) * 72 + ks + tig * 2];
                unsigned a0 = *(const unsigned*)app;
                unsigned a1 = *(const unsigned*)(app + 8 * 72);
                unsigned a2 = *(const unsigned*)(app + 8);
                unsigned a3 = *(const unsigned*)(app + 8 * 72 + 8);
                #pragma unroll
                for (int nt = 0; nt < 2; nt++)
                    mma_bf16(acc[mt][nt], a0, a1, a2, a3, b0[nt], b1[nt]);
            }
        }
        __syncthreads();
    }

    #pragma unroll
    for (int mt = 0; mt < 2; mt++) {
        int sl = wm + mt * 16 + gid;
        int s = i0 + sl;
        float inv0 = sInv[sl];
        float inv1 = sInv[sl + 8];
        #pragma unroll
        for (int nt = 0; nt < 2; nt++) {
            int c = h * 64 + wn + nt * 8 + tig * 2;
            float2 v0 = {acc[mt][nt][0] * inv0, acc[mt][nt][1] * inv0};
            float2 v1 = {acc[mt][nt][2] * inv1, acc[mt][nt][3] * inv1};
            *(float2*)&g_ctx[(size_t)(b * S_ + s) * 768 + c]     = v0;
            *(float2*)&g_ctx[(size_t)(b * S_ + s + 8) * 768 + c] = v1;
        }
    }
    __syncthreads();
}

// ---------------------------------------------------------------------------
// The single fused kernel.
// ---------------------------------------------------------------------------
__global__ __launch_bounds__(NTHR, 2)
void fused_kernel(const float* __restrict__ query, const float* __restrict__ key,
                  const float* __restrict__ value, const float* __restrict__ mask,
                  const float* __restrict__ Wq, const float* __restrict__ bq,
                  const float* __restrict__ Wk, const float* __restrict__ bk,
                  const float* __restrict__ Wv, const float* __restrict__ bv,
                  const float* __restrict__ Wo, const float* __restrict__ bo,
                  const float* __restrict__ gamma, const float* __restrict__ beta,
                  float* __restrict__ out, float* __restrict__ attn_out) {
    extern __shared__ float smem[];
    const int tid  = threadIdx.x;
    const int warp = tid >> 5, lane = tid & 31;

    // ---- Phase 1: QKV projections (3 x 384 tile jobs, tf32 BK=64) ----
    for (int job = blockIdx.x; job < 3 * 384; job += NBLK) {
        int which = job / 384;
        int t = job % 384;
        const float* A  = (which == 0) ? query : (which == 1) ? key : value;
        const float* W  = (which == 0) ? Wq    : (which == 1) ? Wk  : Wv;
        const float* bb = (which == 0) ? bq    : (which == 1) ? bk  : bv;
        float* O        = (which == 0) ? g_q   : (which == 1) ? g_k : g_v;
        gemm_tile_tf32(A, W, bb, O, t, smem, smem + 8704);
    }
    grid_barrier();

    // ---- Phase 2: fused score + exp + partial row sums (6144 jobs) ----
    for (int t = blockIdx.x; t < 6144; t += NBLK)
        score_exp_tile(t, mask, smem, smem + 8704, smem + 17408, smem + 17920);
    grid_barrier();

    // ---- Phase 3: per-row inverse sums ----
    for (int row = blockIdx.x * NTHR + tid; row < 98304; row += NBLK * NTHR) {
        const float* pp = g_part + (size_t)row * 8;
        float4 a = *(const float4*)pp;
        float4 b4 = *(const float4*)(pp + 4);
        g_inv[row] = 1.0f / (a.x + a.y + a.z + a.w + b4.x + b4.y + b4.z + b4.w);
    }
    grid_barrier();

    // ---- Phase 4: context + normalized prob output (768 jobs, bf16) ----
    for (int t = blockIdx.x; t < 768; t += NBLK)
        ctx_tile(t, attn_out, smem);
    grid_barrier();

    // ---- Phase 5: output projection (384 jobs, bf16) ----
    for (int t = blockIdx.x; t < 384; t += NBLK)
        gemm_tile_bf16(g_ctx, Wo, bo, g_proj, t, smem);
    grid_barrier();

    // ---- Phase 6: residual + LayerNorm — warp per row ----
    for (int row = blockIdx.x * 16 + warp; row < MROWS; row += NBLK * 16) {
        const float* pp = g_proj + (size_t)row * 768;
        const float* op = query + (size_t)row * 768;

        float4 x[6];
        float sum = 0.0f;
        #pragma unroll
        for (int v = 0; v < 6; v++) {
            int off = v * 128 + lane * 4;
            float4 a = *(const float4*)&pp[off];
            float4 o = *(const float4*)&op[off];
            x[v].x = a.x + o.x; x[v].y = a.y + o.y;
            x[v].z = a.z + o.z; x[v].w = a.w + o.w;
            sum += x[v].x + x[v].y + x[v].z + x[v].w;
        }
        #pragma unroll
        for (int o = 16; o > 0; o >>= 1)
            sum += __shfl_xor_sync(0xFFFFFFFFu, sum, o);
        const float mu = sum * (1.0f / 768.0f);

        float var = 0.0f;
        #pragma unroll
        for (int v = 0; v < 6; v++) {
            float dx = x[v].x - mu, dy = x[v].y - mu;
            float dz = x[v].z - mu, dw = x[v].w - mu;
            var += dx * dx + dy * dy + dz * dz + dw * dw;
        }
        #pragma unroll
        for (int o = 16; o > 0; o >>= 1)
            var += __shfl_xor_sync(0xFFFFFFFFu, var, o);
        const float inv = rsqrtf(var * (1.0f / 768.0f) + 1e-8f);

        #pragma unroll
        for (int v = 0; v < 6; v++) {
            int off = v * 128 + lane * 4;
            float4 g = *(const float4*)&gamma[off];
            float4 bt = *(const float4*)&beta[off];
            float4 r;
            r.x = (x[v].x - mu) * inv * g.x + bt.x;
            r.y = (x[v].y - mu) * inv * g.y + bt.y;
            r.z = (x[v].z - mu) * inv * g.z + bt.z;
            r.w = (x[v].w - mu) * inv * g.w + bt.w;
            *(float4*)&out[(size_t)row * 768 + off] = r;
        }
    }
}

// ---------------------------------------------------------------------------
// Launch
// ---------------------------------------------------------------------------
extern "C" void kernel_launch(void* const* d_in, const int* in_sizes, int n_in,
                              void* d_out, int out_size) {
    const float* big[3]  = {0, 0, 0};
    const float* mats[4] = {0, 0, 0, 0};
    const float* vecs[6] = {0, 0, 0, 0, 0, 0};
    const float* mask = 0;
    int nb = 0, nm = 0, nv = 0;
    for (int i = 0; i < n_in; i++) {
        const float* p = (const float*)d_in[i];
        switch (in_sizes[i]) {
            case 6291456: if (nb < 3) big[nb++] = p;  break;
            case 589824:  if (nm < 4) mats[nm++] = p; break;
            case 768:     if (nv < 6) vecs[nv++] = p; break;
            case 8192:    mask = p;                   break;
            default: break;
        }
    }
    float* out = (float*)d_out;
    float* attn_out = ((long long)out_size >= (long long)BSD + BHSS)
                          ? (out + BSD) : 0;

    cudaFuncSetAttribute(fused_kernel,
                         cudaFuncAttributeMaxDynamicSharedMemorySize, DYN_SMEM);

    fused_kernel<<<NBLK, NTHR, DYN_SMEM>>>(big[0], big[1], big[2], mask,
                                           mats[0], vecs[0], mats[1], vecs[1],
                                           mats[2], vecs[2], mats[3], vecs[3],
                                           vecs[4], vecs[5], out, attn_out);
}